// round 15
// baseline (speedup 1.0000x reference)
#include <cuda_runtime.h>

// ---------------- problem constants ----------------
#define SEQ   320
#define HH    400          // hidden size H
#define NG    1600         // 4*H gate width
#define BI2   800          // 2*H bilstm output width
#define WDIM  300
#define TDIM  100
#define INDIM 400

// LSTM distribution: 67 blocks per direction, 6 hidden units each (last block 4)
#define GSZ   67
#define KB    6

// ---------------- device scratch (no allocations allowed) ----------------
__device__ float d_x[SEQ * INDIM];        // embedded input
__device__ float d_g0[SEQ * NG];          // precomputed x@W_ih^T + biases (fwd)
__device__ float d_g1[SEQ * NG];          // (bwd)
__device__ float d_hv0[SEQ * BI2];        // layer-0 bilstm output
__device__ float d_hv1[SEQ * BI2];        // layer-1 bilstm output
__device__ float d_pa[SEQ * NG];          // a = hv@w1a^T + b1
__device__ float d_pb[SEQ * NG];          // b = hv@w1b^T
__device__ __align__(16) float d_hbuf[2][2][HH];  // [dir][parity][H] h exchange
// one flag per producer block, PADDED to a private 128B L2 line (R8 protocol —
// best measured; unpadded flags caused the R7 LTS-slice pileup)
__device__ int   d_hflag[2][GSZ][32];
__device__ int   d_done;                  // end-of-kernel reset barrier

// ---------------- math helpers ----------------
__device__ __forceinline__ float sigm_f(float x) {
    float e = __expf(-x);
    return 1.0f / (1.0f + e);
}
__device__ __forceinline__ float tanh_f(float x) {
    float e = __expf(2.0f * x);
    return 1.0f - 2.0f / (e + 1.0f);   // exact limits at +-inf
}

// ---------------- embedding concat ----------------
__global__ void embed_kernel(const int* __restrict__ words, const int* __restrict__ tags,
                             const float* __restrict__ wemb, const float* __restrict__ temb) {
    int idx = blockIdx.x * blockDim.x + threadIdx.x;
    if (idx >= SEQ * INDIM) return;
    int t = idx / INDIM, d = idx % INDIM;
    d_x[idx] = (d < WDIM) ? wemb[words[t] * WDIM + d]
                          : temb[tags[t] * TDIM + (d - WDIM)];
}

// ---------------- dual GEMM: z=0/1 select B/bias/C; C[M,N] = A*B^T + b0 + b1 ----
__global__ void __launch_bounds__(256) gemm_tn2(
    const float* __restrict__ A, int lda,
    const float* __restrict__ B0, const float* __restrict__ B1, int ldb,
    const float* __restrict__ b00, const float* __restrict__ b01,
    const float* __restrict__ b10, const float* __restrict__ b11,
    float* __restrict__ C0, float* __restrict__ C1, int K)
{
    const float* B     = blockIdx.z ? B1  : B0;
    const float* bias0 = blockIdx.z ? b10 : b00;
    const float* bias1 = blockIdx.z ? b11 : b01;
    float*       C     = blockIdx.z ? C1  : C0;

    __shared__ float As[16][68];
    __shared__ float Bs[16][68];
    int tid = threadIdx.x;
    int bm = blockIdx.y * 64, bn = blockIdx.x * 64;
    int row = tid >> 2, kq = tid & 3;      // loaders
    int ty  = tid >> 4, tx = tid & 15;     // compute 4x4 each
    float acc[4][4] = {};

    for (int k0 = 0; k0 < K; k0 += 16) {
        __syncthreads();
        float4 av = *(const float4*)&A[(bm + row) * lda + k0 + kq * 4];
        float4 bv = *(const float4*)&B[(bn + row) * ldb + k0 + kq * 4];
        As[kq*4+0][row] = av.x; As[kq*4+1][row] = av.y;
        As[kq*4+2][row] = av.z; As[kq*4+3][row] = av.w;
        Bs[kq*4+0][row] = bv.x; Bs[kq*4+1][row] = bv.y;
        Bs[kq*4+2][row] = bv.z; Bs[kq*4+3][row] = bv.w;
        __syncthreads();
        #pragma unroll
        for (int kk = 0; kk < 16; kk++) {
            float4 a4 = *(const float4*)&As[kk][ty * 4];
            float4 b4 = *(const float4*)&Bs[kk][tx * 4];
            float aa[4] = {a4.x, a4.y, a4.z, a4.w};
            float bb[4] = {b4.x, b4.y, b4.z, b4.w};
            #pragma unroll
            for (int i = 0; i < 4; i++)
                #pragma unroll
                for (int j = 0; j < 4; j++)
                    acc[i][j] += aa[i] * bb[j];
        }
    }
    #pragma unroll
    for (int i = 0; i < 4; i++) {
        int m = bm + ty * 4 + i;
        #pragma unroll
        for (int j = 0; j < 4; j++) {
            int n = bn + tx * 4 + j;
            float v = acc[i][j];
            if (bias0) v += bias0[n];
            if (bias1) v += bias1[n];
            C[m * NG + n] = v;
        }
    }
}

// ---------------- persistent bidirectional LSTM phase (R8 protocol) ----------
// grid = 2*GSZ blocks, 256 threads. blocks [0,GSZ): forward, [GSZ,2*GSZ): bwd.
// Each block owns KB hidden units; its 4*KB W_hh rows stay resident in smem.
// Per-step sync: producer stores h to d_hbuf, fence, then per-block flag on a
// private 128B line; consumer thread i polls flag i; h picked up via float2.
__global__ void __launch_bounds__(256, 1) lstm_phase(
    const float* __restrict__ whh_f, const float* __restrict__ whh_b,
    const float* __restrict__ h0, const float* __restrict__ c0, int h0base,
    const float* __restrict__ gpre_f, const float* __restrict__ gpre_b,
    float* __restrict__ hv_out)
{
    __shared__ __align__(16) float Ws[4 * KB][HH];   // 38.4 KB
    __shared__ __align__(16) float h_s[HH + 2];
    __shared__ float g_s[4 * KB];
    __shared__ float gp_s[4 * KB];
    __shared__ float c_s[KB];
    __shared__ int   last_s;

    const int tid  = threadIdx.x;
    const int dir  = (blockIdx.x >= GSZ) ? 1 : 0;
    const int slot = dir ? (blockIdx.x - GSZ) : blockIdx.x;
    const int k0   = slot * KB;
    const int kn   = min(KB, HH - k0);   // last block covers 4
    const float* whh  = dir ? whh_b  : whh_f;
    const float* gpre = dir ? gpre_b : gpre_f;
    const int h0row = h0base + dir;

    // preload W_hh slice: smem row r = gate*KB + kk  <->  W_hh row gate*HH + k0 + kk
    for (int idx = tid; idx < 4 * KB * HH; idx += blockDim.x) {
        int r = idx / HH, m = idx - r * HH;
        int g = r / KB, kk = r - g * KB;
        Ws[r][m] = (kk < kn) ? whh[(g * HH + k0 + kk) * HH + m] : 0.0f;
    }
    if (tid < KB) c_s[tid] = (tid < kn) ? c0[h0row * HH + k0 + tid] : 0.0f;
    if (tid == 0) last_s = 0;
    __syncthreads();

    const int wid = tid >> 5, lane = tid & 31;
    volatile int* myflag = &d_hflag[dir][slot][0];
    volatile int* pollfl = (tid < GSZ) ? &d_hflag[dir][tid][0] : 0;

    for (int s = 0; s < SEQ; s++) {
        const int t = dir ? (SEQ - 1 - s) : s;   // physical time index

        // gate-input prefetch on warp 4 (NOT pollers) so pollers spin instantly
        if (tid >= 128 && tid < 128 + 4 * KB) {
            int r = tid - 128;
            int g = r / KB, kk = r - g * KB;
            gp_s[r] = (kk < kn) ? __ldg(&gpre[t * NG + g * HH + k0 + kk]) : 0.0f;
        }
        // wait: all blocks of this direction must have published h(s-1);
        // each poll thread spins on its own 128B line
        if (s > 0 && tid < GSZ) {
            while (*pollfl < s) { }
        }
        __syncthreads();

        // load h (L2-coherent, float2-vectorized: 200 loads instead of 400)
        if (s == 0) {
            for (int m = tid; m < HH; m += blockDim.x) h_s[m] = h0[h0row * HH + m];
        } else if (tid < HH / 2) {
            const float2* hsrc = (const float2*)d_hbuf[dir][s & 1];
            float2 v = __ldcg(&hsrc[tid]);
            h_s[2 * tid]     = v.x;
            h_s[2 * tid + 1] = v.y;
        }
        __syncthreads();

        // 24 dot products of length 400; warp w handles rows w, w+8, w+16
        {
            const float* w0  = Ws[wid];
            const float* w1  = Ws[wid + 8];
            const float* w2p = Ws[wid + 16];
            float s0 = 0.f, s1 = 0.f, s2 = 0.f;
            #pragma unroll
            for (int u = 0; u < 12; u++) {
                int m = lane + u * 32;
                float hv = h_s[m];
                s0 += w0[m] * hv; s1 += w1[m] * hv; s2 += w2p[m] * hv;
            }
            {   // tail: elements 384..399 (lanes 0..15)
                int m = lane + 384;
                if (m < HH) {
                    float hv = h_s[m];
                    s0 += w0[m] * hv; s1 += w1[m] * hv; s2 += w2p[m] * hv;
                }
            }
            #pragma unroll
            for (int off = 16; off; off >>= 1) {
                s0 += __shfl_xor_sync(0xffffffffu, s0, off);
                s1 += __shfl_xor_sync(0xffffffffu, s1, off);
                s2 += __shfl_xor_sync(0xffffffffu, s2, off);
            }
            if (lane == 0) {
                g_s[wid]      = s0 + gp_s[wid];
                g_s[wid + 8]  = s1 + gp_s[wid + 8];
                g_s[wid + 16] = s2 + gp_s[wid + 16];
            }
        }
        __syncthreads();

        // gate nonlinearities + state update (warp 0 only: tid < kn <= 6)
        float hval = 0.0f;
        if (tid < kn) {
            float gi = g_s[0 * KB + tid];
            float gf = g_s[1 * KB + tid];
            float gg = g_s[2 * KB + tid];
            float go = g_s[3 * KB + tid];
            float i = sigm_f(gi), f = sigm_f(gf), o = sigm_f(go);
            float c = f * c_s[tid] + i * tanh_f(gg);
            c_s[tid] = c;
            hval = o * tanh_f(c);
            d_hbuf[dir][(s + 1) & 1][k0 + tid] = hval;
        }
        // publish FIRST (critical path), archive hv_out after
        __syncwarp();
        if (tid == 0 && s < SEQ - 1) {
            __threadfence();
            *myflag = s + 1;
        }
        if (tid < kn) {
            hv_out[t * BI2 + dir * HH + k0 + tid] = hval;
        }
        // warps 1..7 proceed; they re-converge at the next __syncthreads
    }

    // end-of-kernel barrier: last block to arrive resets all flags for replay
    __syncthreads();
    if (tid == 0) {
        __threadfence();
        int v = atomicAdd(&d_done, 1) + 1;
        last_s = (v == 2 * GSZ);
    }
    __syncthreads();
    if (last_s) {
        int* fl = (int*)d_hflag;
        for (int i = tid; i < 2 * GSZ * 32; i += blockDim.x) fl[i] = 0;
        __syncthreads();
        if (tid == 0) { __threadfence(); d_done = 0; }
    }
}

// ---------------- output border init ----------------
__global__ void init_out(float* __restrict__ out) {
    int i = blockIdx.x * blockDim.x + threadIdx.x;
    if (i <= SEQ) {
        out[i]       = (i == 0) ? 1.0f : 0.0f;   // row 0
        out[i * 321] = (i == 0) ? 1.0f : 0.0f;   // col 0
    }
}

// ---------------- pairwise biaffine-style scores ----------------
// out[1+i][1+j] = (i==j) ? 0 : sum_k relu(a[i,k]+b[j,k])*w2[k] + b2
__global__ void __launch_bounds__(256) pairwise_kernel(
    const float* __restrict__ A, const float* __restrict__ Bm,
    const float* __restrict__ w2, const float* __restrict__ b2,
    float* __restrict__ out)
{
    __shared__ float As[32][34], Bs[32][34], w2s[32];
    int tid = threadIdx.x;
    int bi = blockIdx.y * 32, bj = blockIdx.x * 32;
    int ty = tid >> 4, tx = tid & 15;
    int row = tid >> 3, kq = tid & 7;
    float a00 = 0.f, a01 = 0.f, a10 = 0.f, a11 = 0.f;

    for (int k0 = 0; k0 < NG; k0 += 32) {
        __syncthreads();
        float4 av = *(const float4*)&A [(bi + row) * NG + k0 + kq * 4];
        float4 bv = *(const float4*)&Bm[(bj + row) * NG + k0 + kq * 4];
        As[kq*4+0][row] = av.x; As[kq*4+1][row] = av.y;
        As[kq*4+2][row] = av.z; As[kq*4+3][row] = av.w;
        Bs[kq*4+0][row] = bv.x; Bs[kq*4+1][row] = bv.y;
        Bs[kq*4+2][row] = bv.z; Bs[kq*4+3][row] = bv.w;
        if (tid < 32) w2s[tid] = w2[k0 + tid];
        __syncthreads();
        #pragma unroll
        for (int kk = 0; kk < 32; kk++) {
            float w = w2s[kk];
            float2 a = *(const float2*)&As[kk][ty * 2];
            float2 b = *(const float2*)&Bs[kk][tx * 2];
            a00 += fmaxf(a.x + b.x, 0.f) * w;
            a01 += fmaxf(a.x + b.y, 0.f) * w;
            a10 += fmaxf(a.y + b.x, 0.f) * w;
            a11 += fmaxf(a.y + b.y, 0.f) * w;
        }
    }
    float bb = b2[0];
    int gi = bi + ty * 2, gj = bj + tx * 2;
    out[(gi + 1) * 321 + (gj + 1)] = (gi     == gj    ) ? 0.f : a00 + bb;
    out[(gi + 1) * 321 + (gj + 2)] = (gi     == gj + 1) ? 0.f : a01 + bb;
    out[(gi + 2) * 321 + (gj + 1)] = (gi + 1 == gj    ) ? 0.f : a10 + bb;
    out[(gi + 2) * 321 + (gj + 2)] = (gi     == gj    ) ? 0.f : a11 + bb;
}

// ---------------- host orchestration ----------------
extern "C" void kernel_launch(void* const* d_in, const int* in_sizes, int n_in,
                              void* d_out, int out_size) {
    const int*   words    = (const int*)  d_in[0];
    const int*   tags     = (const int*)  d_in[1];
    const float* wemb     = (const float*)d_in[3];
    const float* temb     = (const float*)d_in[4];
    const float* h0       = (const float*)d_in[5];
    const float* c0       = (const float*)d_in[6];
    const float* w_ih_l0  = (const float*)d_in[7];
    const float* w_hh_l0  = (const float*)d_in[8];
    const float* b_ih_l0  = (const float*)d_in[9];
    const float* b_hh_l0  = (const float*)d_in[10];
    const float* w_ih_l0r = (const float*)d_in[11];
    const float* w_hh_l0r = (const float*)d_in[12];
    const float* b_ih_l0r = (const float*)d_in[13];
    const float* b_hh_l0r = (const float*)d_in[14];
    const float* w_ih_l1  = (const float*)d_in[15];
    const float* w_hh_l1  = (const float*)d_in[16];
    const float* b_ih_l1  = (const float*)d_in[17];
    const float* b_hh_l1  = (const float*)d_in[18];
    const float* w_ih_l1r = (const float*)d_in[19];
    const float* w_hh_l1r = (const float*)d_in[20];
    const float* b_ih_l1r = (const float*)d_in[21];
    const float* b_hh_l1r = (const float*)d_in[22];
    const float* mlp_w1   = (const float*)d_in[23];
    const float* mlp_b1   = (const float*)d_in[24];
    const float* mlp_w2   = (const float*)d_in[25];
    const float* mlp_b2   = (const float*)d_in[26];
    float* out = (float*)d_out;

    // addresses of device scratch
    float *px, *pg0, *pg1, *phv0, *phv1, *pa, *pb;
    cudaGetSymbolAddress((void**)&px,   d_x);
    cudaGetSymbolAddress((void**)&pg0,  d_g0);
    cudaGetSymbolAddress((void**)&pg1,  d_g1);
    cudaGetSymbolAddress((void**)&phv0, d_hv0);
    cudaGetSymbolAddress((void**)&phv1, d_hv1);
    cudaGetSymbolAddress((void**)&pa,   d_pa);
    cudaGetSymbolAddress((void**)&pb,   d_pb);

    dim3 gg(NG / 64, SEQ / 64, 2);   // (25, 5, 2)

    // launch order chosen so that profile index 5 (ncu -s 5 -c 1) lands on
    // lstm_phase (layer 1) — the kernel we actually need metrics for.
    // idx 0: embeddings
    embed_kernel<<<(SEQ * INDIM + 255) / 256, 256>>>(words, tags, wemb, temb);

    // idx 1: layer-0 input projections fwd+bwd (biases folded in)
    gemm_tn2<<<gg, 256>>>(px, INDIM, w_ih_l0, w_ih_l0r, INDIM,
                          b_ih_l0, b_hh_l0, b_ih_l0r, b_hh_l0r,
                          pg0, pg1, INDIM);

    // idx 2: layer-0 bilstm (persistent, 134 blocks)
    lstm_phase<<<2 * GSZ, 256>>>(w_hh_l0, w_hh_l0r, h0, c0, 0, pg0, pg1, phv0);

    // idx 3: layer-1 input projections fwd+bwd
    gemm_tn2<<<gg, 256>>>(phv0, BI2, w_ih_l1, w_ih_l1r, BI2,
                          b_ih_l1, b_hh_l1, b_ih_l1r, b_hh_l1r,
                          pg0, pg1, BI2);

    // idx 4: output borders (independent of LSTM results)
    init_out<<<2, 256>>>(out);

    // idx 5: layer-1 bilstm  <-- profiled launch
    lstm_phase<<<2 * GSZ, 256>>>(w_hh_l1, w_hh_l1r, h0, c0, 2, pg0, pg1, phv1);

    // idx 6: MLP split projections: a = hv@w1a^T + b1 ; b = hv@w1b^T
    gemm_tn2<<<gg, 256>>>(phv1, BI2, mlp_w1, mlp_w1 + BI2, NG,
                          mlp_b1, nullptr, nullptr, nullptr,
                          pa, pb, BI2);

    // idx 7: pairwise scores
    pairwise_kernel<<<dim3(10, 10), 256>>>(pa, pb, mlp_w2, mlp_b2, out);
}

// round 16
// speedup vs baseline: 1.6269x; 1.6269x over previous
#include <cuda_runtime.h>

// ---------------- problem constants ----------------
#define SEQ   320
#define HH    400          // hidden size H
#define NG    1600         // 4*H gate width
#define BI2   800          // 2*H bilstm output width
#define WDIM  300
#define TDIM  100
#define INDIM 400

// Fused-direction LSTM distribution: 67 blocks TOTAL (was 134).
// Each block owns KB=6 fwd units AND KB=6 bwd units (last block 4+4).
#define GSZ   67
#define KB    6
#define ROWS  48           // 2 dirs * 4 gates * KB rows resident per block
#define HOFF  416          // bwd h offset inside h_s (400 used + pad)
#define DSMEM (ROWS * HH * 4)   // 76800 B dynamic smem for Ws

// ---------------- device scratch (no allocations allowed) ----------------
__device__ float d_x[SEQ * INDIM];
__device__ float d_g0[SEQ * NG];          // x@W_ih^T + biases (fwd)
__device__ float d_g1[SEQ * NG];          // (bwd)
__device__ float d_hv0[SEQ * BI2];
__device__ float d_hv1[SEQ * BI2];
__device__ float d_pa[SEQ * NG];
__device__ float d_pb[SEQ * NG];
// h publication lines: [parity][slot][16 u64 packets] = one 128B line each.
// Packets 0..5 = fwd units, 6..11 = bwd units (12..15 unused).
// Each packet = (tag<<32 | h_bits), st.relaxed.gpu.u64 -> single-copy atomic.
__device__ __align__(128) unsigned long long d_hline[2][GSZ][16];
__device__ int d_done;

// ---------------- math helpers ----------------
__device__ __forceinline__ float sigm_f(float x) {
    float e = __expf(-x);
    return 1.0f / (1.0f + e);
}
__device__ __forceinline__ float tanh_f(float x) {
    float e = __expf(2.0f * x);
    return 1.0f - 2.0f / (e + 1.0f);
}
__device__ __forceinline__ void st_pkt(unsigned long long* p, float v, unsigned int tag) {
    unsigned long long pk = ((unsigned long long)tag << 32) |
                            (unsigned long long)__float_as_uint(v);
    asm volatile("st.relaxed.gpu.u64 [%0], %1;" :: "l"(p), "l"(pk) : "memory");
}
__device__ __forceinline__ unsigned long long ld_pkt(const unsigned long long* p) {
    unsigned long long r;
    asm volatile("ld.relaxed.gpu.u64 %0, [%1];" : "=l"(r) : "l"(p) : "memory");
    return r;
}

// ---------------- embedding concat ----------------
__global__ void embed_kernel(const int* __restrict__ words, const int* __restrict__ tags,
                             const float* __restrict__ wemb, const float* __restrict__ temb) {
    int idx = blockIdx.x * blockDim.x + threadIdx.x;
    if (idx >= SEQ * INDIM) return;
    int t = idx / INDIM, d = idx % INDIM;
    d_x[idx] = (d < WDIM) ? wemb[words[t] * WDIM + d]
                          : temb[tags[t] * TDIM + (d - WDIM)];
}

// ---------------- dual GEMM: z=0/1 select B/bias/C; C[M,N] = A*B^T + b0 + b1 ----
__global__ void __launch_bounds__(256) gemm_tn2(
    const float* __restrict__ A, int lda,
    const float* __restrict__ B0, const float* __restrict__ B1, int ldb,
    const float* __restrict__ b00, const float* __restrict__ b01,
    const float* __restrict__ b10, const float* __restrict__ b11,
    float* __restrict__ C0, float* __restrict__ C1, int K)
{
    const float* B     = blockIdx.z ? B1  : B0;
    const float* bias0 = blockIdx.z ? b10 : b00;
    const float* bias1 = blockIdx.z ? b11 : b01;
    float*       C     = blockIdx.z ? C1  : C0;

    __shared__ float As[16][68];
    __shared__ float Bs[16][68];
    int tid = threadIdx.x;
    int bm = blockIdx.y * 64, bn = blockIdx.x * 64;
    int row = tid >> 2, kq = tid & 3;
    int ty  = tid >> 4, tx = tid & 15;
    float acc[4][4] = {};

    for (int k0 = 0; k0 < K; k0 += 16) {
        __syncthreads();
        float4 av = *(const float4*)&A[(bm + row) * lda + k0 + kq * 4];
        float4 bv = *(const float4*)&B[(bn + row) * ldb + k0 + kq * 4];
        As[kq*4+0][row] = av.x; As[kq*4+1][row] = av.y;
        As[kq*4+2][row] = av.z; As[kq*4+3][row] = av.w;
        Bs[kq*4+0][row] = bv.x; Bs[kq*4+1][row] = bv.y;
        Bs[kq*4+2][row] = bv.z; Bs[kq*4+3][row] = bv.w;
        __syncthreads();
        #pragma unroll
        for (int kk = 0; kk < 16; kk++) {
            float4 a4 = *(const float4*)&As[kk][ty * 4];
            float4 b4 = *(const float4*)&Bs[kk][tx * 4];
            float aa[4] = {a4.x, a4.y, a4.z, a4.w};
            float bb[4] = {b4.x, b4.y, b4.z, b4.w};
            #pragma unroll
            for (int i = 0; i < 4; i++)
                #pragma unroll
                for (int j = 0; j < 4; j++)
                    acc[i][j] += aa[i] * bb[j];
        }
    }
    #pragma unroll
    for (int i = 0; i < 4; i++) {
        int m = bm + ty * 4 + i;
        #pragma unroll
        for (int j = 0; j < 4; j++) {
            int n = bn + tx * 4 + j;
            float v = acc[i][j];
            if (bias0) v += bias0[n];
            if (bias1) v += bias1[n];
            C[m * NG + n] = v;
        }
    }
}

// ---------------- persistent FUSED bidirectional LSTM phase ----------------
// grid = GSZ=67 blocks, 256 threads. Block `slot` owns fwd units [k0,k0+kn)
// AND bwd units [k0,k0+kn). Ws rows (dynamic smem): r = d*24 + g*KB + u.
// Per step: poll all 67 lines (2 pollers/line, 6 packets each) into parity-
// double-buffered h_s; one GEMV over 48 rows; threads 0..11 apply gates
// (c in registers) and publish 12 packets (tag s+1) in one 128B line.
__global__ void __launch_bounds__(256, 1) lstm_phase(
    const float* __restrict__ whh_f, const float* __restrict__ whh_b,
    const float* __restrict__ h0, const float* __restrict__ c0, int h0base,
    const float* __restrict__ gpre_f, const float* __restrict__ gpre_b,
    float* __restrict__ hv_out)
{
    extern __shared__ float Ws[];                 // [ROWS][HH] row-major
    __shared__ float h_s[2][2 * HOFF];            // fwd @0, bwd @HOFF, per parity
    __shared__ float gp_s[2][ROWS];               // gate inputs, per parity
    __shared__ float g_s[ROWS];                   // row sums (single buffer, safe)
    __shared__ int   last_s;

    const int tid  = threadIdx.x;
    const int slot = blockIdx.x;
    const int k0   = slot * KB;
    const int kn   = min(KB, HH - k0);            // last block: 4

    // preload W_hh rows for BOTH directions
    for (int idx = tid; idx < ROWS * HH; idx += 256) {
        int r = idx / HH, m = idx - r * HH;
        int d = (r >= 24) ? 1 : 0;
        int rr = d ? r - 24 : r;
        int g = rr / KB, u = rr - g * KB;
        const float* w = d ? whh_b : whh_f;
        Ws[r * HH + m] = (u < kn) ? w[(g * HH + k0 + u) * HH + m] : 0.0f;
    }
    if (tid == 0) last_s = 0;

    const int wid = tid >> 5, lane = tid & 31;
    // cell state: thread i<12 keeps c for (dir=i/KB, unit=i%KB) in a register
    float creg = 0.0f;
    if (tid < 2 * KB) {
        int d = tid / KB, u = tid - d * KB;
        if (u < kn) creg = c0[(h0base + d) * HH + k0 + u];
    }
    __syncthreads();

    for (int s = 0; s < SEQ; s++) {
        const int t  = s;
        const int tb = SEQ - 1 - s;
        const int par = s & 1;

        // ---- phase 1 ----
        // gate-input prefetch first (LDG in flight while polling): warps 4-5
        if (tid >= 128 && tid < 128 + ROWS) {
            int r = tid - 128;                    // 0..47
            int d = (r >= 24) ? 1 : 0;
            int rr = d ? r - 24 : r;
            int g = rr / KB, u = rr - g * KB;
            const float* gp = d ? gpre_b : gpre_f;
            int tt = d ? tb : t;
            gp_s[par][r] = (u < kn) ? __ldg(&gp[tt * NG + g * HH + k0 + u]) : 0.0f;
        }
        if (s == 0) {
            for (int m = tid; m < 2 * HH; m += 256) {
                if (m < HH) h_s[0][m] = h0[(h0base + 0) * HH + m];
                else        h_s[0][HOFF + m - HH] = h0[(h0base + 1) * HH + (m - HH)];
            }
        } else if (tid < 2 * GSZ) {               // 134 pollers, 2 per line
            int line = tid >> 1, half = tid & 1;  // half0=fwd pkts 0-5, half1=bwd 6-11
            const unsigned long long* lp = &d_hline[par][line][half * KB];
            const unsigned long long tg = (unsigned long long)(unsigned int)s;
            unsigned long long q0, q1, q2, q3, q4, q5;
            do {
                q0 = ld_pkt(lp + 0); q1 = ld_pkt(lp + 1); q2 = ld_pkt(lp + 2);
                q3 = ld_pkt(lp + 3); q4 = ld_pkt(lp + 4); q5 = ld_pkt(lp + 5);
            } while ((((q0 >> 32) ^ tg) | ((q1 >> 32) ^ tg) | ((q2 >> 32) ^ tg) |
                      ((q3 >> 32) ^ tg) | ((q4 >> 32) ^ tg) | ((q5 >> 32) ^ tg)) != 0ull);
            float* dst = h_s[par] + half * HOFF + line * KB;   // pads absorb dummies
            dst[0] = __uint_as_float((unsigned int)q0);
            dst[1] = __uint_as_float((unsigned int)q1);
            dst[2] = __uint_as_float((unsigned int)q2);
            dst[3] = __uint_as_float((unsigned int)q3);
            dst[4] = __uint_as_float((unsigned int)q4);
            dst[5] = __uint_as_float((unsigned int)q5);
        }
        __syncthreads();   // barrier A: h_s[par] + gp_s[par] ready

        // ---- phase 2: GEMV, warp w -> rows w+8j (j<3 fwd, j>=3 bwd) ----
        {
            const float* hf  = h_s[par];
            const float* hbp = h_s[par] + HOFF;
            const float* wp  = Ws + wid * HH;
            float a0 = 0.f, a1 = 0.f, a2 = 0.f, a3 = 0.f, a4 = 0.f, a5 = 0.f;
            #pragma unroll
            for (int k = 0; k < 12; k++) {
                int m = lane + 32 * k;
                float hfv = hf[m], hbv = hbp[m];
                a0 += wp[ 0 * HH + m] * hfv;
                a1 += wp[ 8 * HH + m] * hfv;
                a2 += wp[16 * HH + m] * hfv;
                a3 += wp[24 * HH + m] * hbv;
                a4 += wp[32 * HH + m] * hbv;
                a5 += wp[40 * HH + m] * hbv;
            }
            if (lane < 16) {                      // tail 384..399
                int m = 384 + lane;
                float hfv = hf[m], hbv = hbp[m];
                a0 += wp[ 0 * HH + m] * hfv;
                a1 += wp[ 8 * HH + m] * hfv;
                a2 += wp[16 * HH + m] * hfv;
                a3 += wp[24 * HH + m] * hbv;
                a4 += wp[32 * HH + m] * hbv;
                a5 += wp[40 * HH + m] * hbv;
            }
            #pragma unroll
            for (int off = 16; off; off >>= 1) {
                a0 += __shfl_xor_sync(0xffffffffu, a0, off);
                a1 += __shfl_xor_sync(0xffffffffu, a1, off);
                a2 += __shfl_xor_sync(0xffffffffu, a2, off);
                a3 += __shfl_xor_sync(0xffffffffu, a3, off);
                a4 += __shfl_xor_sync(0xffffffffu, a4, off);
                a5 += __shfl_xor_sync(0xffffffffu, a5, off);
            }
            if (lane == 0) {
                g_s[wid]      = a0; g_s[wid +  8] = a1; g_s[wid + 16] = a2;
                g_s[wid + 24] = a3; g_s[wid + 32] = a4; g_s[wid + 40] = a5;
            }
        }
        __syncthreads();   // barrier B: g_s ready

        // ---- phase 3: gates + publish (threads 0..11) ----
        if (tid < 2 * KB) {
            int d = tid / KB, u = tid - d * KB;
            int rb = d * 24 + u;
            const float* gp = gp_s[par];
            float gi = g_s[rb]          + gp[rb];
            float gf = g_s[rb + KB]     + gp[rb + KB];
            float gg = g_s[rb + 2 * KB] + gp[rb + 2 * KB];
            float go = g_s[rb + 3 * KB] + gp[rb + 3 * KB];
            float i = sigm_f(gi), f = sigm_f(gf), o = sigm_f(go);
            creg = f * creg + i * tanh_f(gg);
            float hval = (u < kn) ? o * tanh_f(creg) : 0.0f;
            if (s < SEQ - 1)
                st_pkt(&d_hline[(s + 1) & 1][slot][tid], hval, (unsigned int)(s + 1));
            if (u < kn) {
                int tt = d ? tb : t;
                hv_out[tt * BI2 + d * HH + k0 + u] = hval;
            }
        }
        // no barrier: parity double-buffers + barrier-A ordering make it safe
    }

    // end-of-kernel: last block resets all lines for graph replay
    __syncthreads();
    if (tid == 0) {
        __threadfence();
        int v = atomicAdd(&d_done, 1) + 1;
        last_s = (v == GSZ);
    }
    __syncthreads();
    if (last_s) {
        unsigned long long* fl = &d_hline[0][0][0];
        for (int i = tid; i < 2 * GSZ * 16; i += 256) fl[i] = 0ull;
        __syncthreads();
        if (tid == 0) { __threadfence(); d_done = 0; }
    }
}

// ---------------- output border init ----------------
__global__ void init_out(float* __restrict__ out) {
    int i = blockIdx.x * blockDim.x + threadIdx.x;
    if (i <= SEQ) {
        out[i]       = (i == 0) ? 1.0f : 0.0f;
        out[i * 321] = (i == 0) ? 1.0f : 0.0f;
    }
}

// ---------------- pairwise biaffine-style scores ----------------
__global__ void __launch_bounds__(256) pairwise_kernel(
    const float* __restrict__ A, const float* __restrict__ Bm,
    const float* __restrict__ w2, const float* __restrict__ b2,
    float* __restrict__ out)
{
    __shared__ float As[32][34], Bs[32][34], w2s[32];
    int tid = threadIdx.x;
    int bi = blockIdx.y * 32, bj = blockIdx.x * 32;
    int ty = tid >> 4, tx = tid & 15;
    int row = tid >> 3, kq = tid & 7;
    float a00 = 0.f, a01 = 0.f, a10 = 0.f, a11 = 0.f;

    for (int k0 = 0; k0 < NG; k0 += 32) {
        __syncthreads();
        float4 av = *(const float4*)&A [(bi + row) * NG + k0 + kq * 4];
        float4 bv = *(const float4*)&Bm[(bj + row) * NG + k0 + kq * 4];
        As[kq*4+0][row] = av.x; As[kq*4+1][row] = av.y;
        As[kq*4+2][row] = av.z; As[kq*4+3][row] = av.w;
        Bs[kq*4+0][row] = bv.x; Bs[kq*4+1][row] = bv.y;
        Bs[kq*4+2][row] = bv.z; Bs[kq*4+3][row] = bv.w;
        if (tid < 32) w2s[tid] = w2[k0 + tid];
        __syncthreads();
        #pragma unroll
        for (int kk = 0; kk < 32; kk++) {
            float w = w2s[kk];
            float2 a = *(const float2*)&As[kk][ty * 2];
            float2 b = *(const float2*)&Bs[kk][tx * 2];
            a00 += fmaxf(a.x + b.x, 0.f) * w;
            a01 += fmaxf(a.x + b.y, 0.f) * w;
            a10 += fmaxf(a.y + b.x, 0.f) * w;
            a11 += fmaxf(a.y + b.y, 0.f) * w;
        }
    }
    float bb = b2[0];
    int gi = bi + ty * 2, gj = bj + tx * 2;
    out[(gi + 1) * 321 + (gj + 1)] = (gi     == gj    ) ? 0.f : a00 + bb;
    out[(gi + 1) * 321 + (gj + 2)] = (gi     == gj + 1) ? 0.f : a01 + bb;
    out[(gi + 2) * 321 + (gj + 1)] = (gi + 1 == gj    ) ? 0.f : a10 + bb;
    out[(gi + 2) * 321 + (gj + 2)] = (gi     == gj    ) ? 0.f : a11 + bb;
}

// ---------------- host orchestration ----------------
extern "C" void kernel_launch(void* const* d_in, const int* in_sizes, int n_in,
                              void* d_out, int out_size) {
    const int*   words    = (const int*)  d_in[0];
    const int*   tags     = (const int*)  d_in[1];
    const float* wemb     = (const float*)d_in[3];
    const float* temb     = (const float*)d_in[4];
    const float* h0       = (const float*)d_in[5];
    const float* c0       = (const float*)d_in[6];
    const float* w_ih_l0  = (const float*)d_in[7];
    const float* w_hh_l0  = (const float*)d_in[8];
    const float* b_ih_l0  = (const float*)d_in[9];
    const float* b_hh_l0  = (const float*)d_in[10];
    const float* w_ih_l0r = (const float*)d_in[11];
    const float* w_hh_l0r = (const float*)d_in[12];
    const float* b_ih_l0r = (const float*)d_in[13];
    const float* b_hh_l0r = (const float*)d_in[14];
    const float* w_ih_l1  = (const float*)d_in[15];
    const float* w_hh_l1  = (const float*)d_in[16];
    const float* b_ih_l1  = (const float*)d_in[17];
    const float* b_hh_l1  = (const float*)d_in[18];
    const float* w_ih_l1r = (const float*)d_in[19];
    const float* w_hh_l1r = (const float*)d_in[20];
    const float* b_ih_l1r = (const float*)d_in[21];
    const float* b_hh_l1r = (const float*)d_in[22];
    const float* mlp_w1   = (const float*)d_in[23];
    const float* mlp_b1   = (const float*)d_in[24];
    const float* mlp_w2   = (const float*)d_in[25];
    const float* mlp_b2   = (const float*)d_in[26];
    float* out = (float*)d_out;

    float *px, *pg0, *pg1, *phv0, *phv1, *pa, *pb;
    cudaGetSymbolAddress((void**)&px,   d_x);
    cudaGetSymbolAddress((void**)&pg0,  d_g0);
    cudaGetSymbolAddress((void**)&pg1,  d_g1);
    cudaGetSymbolAddress((void**)&phv0, d_hv0);
    cudaGetSymbolAddress((void**)&phv1, d_hv1);
    cudaGetSymbolAddress((void**)&pa,   d_pa);
    cudaGetSymbolAddress((void**)&pb,   d_pb);

    // dynamic smem opt-in (idempotent; not a stream op — capture-safe)
    cudaFuncSetAttribute(lstm_phase, cudaFuncAttributeMaxDynamicSharedMemorySize, DSMEM);

    dim3 gg(NG / 64, SEQ / 64, 2);   // (25, 5, 2)

    embed_kernel<<<(SEQ * INDIM + 255) / 256, 256>>>(words, tags, wemb, temb);

    gemm_tn2<<<gg, 256>>>(px, INDIM, w_ih_l0, w_ih_l0r, INDIM,
                          b_ih_l0, b_hh_l0, b_ih_l0r, b_hh_l0r,
                          pg0, pg1, INDIM);

    lstm_phase<<<GSZ, 256, DSMEM>>>(w_hh_l0, w_hh_l0r, h0, c0, 0, pg0, pg1, phv0);

    gemm_tn2<<<gg, 256>>>(phv0, BI2, w_ih_l1, w_ih_l1r, BI2,
                          b_ih_l1, b_hh_l1, b_ih_l1r, b_hh_l1r,
                          pg0, pg1, BI2);

    lstm_phase<<<GSZ, 256, DSMEM>>>(w_hh_l1, w_hh_l1r, h0, c0, 2, pg0, pg1, phv1);

    gemm_tn2<<<gg, 256>>>(phv1, BI2, mlp_w1, mlp_w1 + BI2, NG,
                          mlp_b1, nullptr, nullptr, nullptr,
                          pa, pb, BI2);

    init_out<<<2, 256>>>(out);
    pairwise_kernel<<<dim3(10, 10), 256>>>(pa, pb, mlp_w2, mlp_b2, out);
}